// round 15
// baseline (speedup 1.0000x reference)
#include <cuda_runtime.h>

// Reference degenerates to: mean over (b, j) of (true[b,10j] - pred[b,10j])^2.
//
// R10: pure DRAM-BW bound at 6.34 TB/s (79% of spec); traffic is minimal
// (every 64B atom holds a sample). Last lever: .L2::256B prefetch-size on
// the loads -> each L2 miss fills a full 256B span, turning the ragged
// sparse-sector fill stream into sequential DRAM bursts (no extra traffic:
// neighboring warps need those atoms and now hit in L2).

#define ROWS   1024
#define NFRM   8192
#define NSAMP  820
#define NTHR   256
#define KPT    4
#define NBLK   820                 // 820*256*4 = 839680 samples exactly
#define SCALE  1073741824.0        // 2^30
// 1 / (SCALE * ROWS * NSAMP)
#define INV_NORM (1.0 / (1073741824.0 * 1024.0 * 820.0))

__device__ unsigned long long g_acc = 0ULL;
__device__ unsigned int       g_cnt = 0u;

struct F8 { float v0, v1, v2, v3, v4, v5, v6, v7; };

__device__ __forceinline__ F8 ldg256_pf(const float* p) {
    F8 r;
    asm volatile(
        "ld.global.L2::evict_last.L2::256B.v8.b32 "
        "{%0,%1,%2,%3,%4,%5,%6,%7}, [%8];"
        : "=f"(r.v0), "=f"(r.v1), "=f"(r.v2), "=f"(r.v3),
          "=f"(r.v4), "=f"(r.v5), "=f"(r.v6), "=f"(r.v7)
        : "l"(p));
    return r;
}

__device__ __forceinline__ float sel_even(const F8& c, unsigned s) {
    // s = j & 3 -> component 2*s
    float lo = (s & 1u) ? c.v2 : c.v0;
    float hi = (s & 1u) ? c.v6 : c.v4;
    return (s & 2u) ? hi : lo;
}

__global__ __launch_bounds__(NTHR)
void mse_fused_kernel(const float* __restrict__ tf,
                      const float* __restrict__ pf,
                      float* __restrict__ out) {
    const unsigned base = blockIdx.x * (NTHR * KPT) + threadIdx.x;

    unsigned elem[KPT];   // element offset of the 32B-aligned chunk
    unsigned sel[KPT];    // j & 3
#pragma unroll
    for (int k = 0; k < KPT; k++) {
        unsigned i   = base + k * NTHR;        // global sample id
        unsigned row = i / NSAMP;              // umulhi + shift
        unsigned j   = i - row * NSAMP;
        unsigned col = 10u * j;
        elem[k] = row * NFRM + (col & ~7u);    // 32B-chunk aligned
        sel[k]  = j & 3u;
    }

    // 32B sector loads with 256B L2 fill hint (sequential DRAM bursts).
    F8 a[KPT], b[KPT];
#pragma unroll
    for (int k = 0; k < KPT; k++) a[k] = ldg256_pf(tf + elem[k]);
#pragma unroll
    for (int k = 0; k < KPT; k++) b[k] = ldg256_pf(pf + elem[k]);

    float acc = 0.0f;
#pragma unroll
    for (int k = 0; k < KPT; k++) {
        float d = sel_even(a[k], sel[k]) - sel_even(b[k], sel[k]);
        acc = fmaf(d, d, acc);
    }

    // Deterministic block reduction: warp shuffle + shared across 8 warps.
    __shared__ float sm[NTHR / 32];
#pragma unroll
    for (int off = 16; off > 0; off >>= 1)
        acc += __shfl_down_sync(0xFFFFFFFFu, acc, off);
    if ((threadIdx.x & 31) == 0) sm[threadIdx.x >> 5] = acc;
    __syncthreads();

    if (threadIdx.x == 0) {
        float v = sm[0];
#pragma unroll
        for (int w = 1; w < NTHR / 32; w++) v += sm[w];

        // Fixed-point: integer adds are associative => deterministic.
        long long qfx = llrint((double)v * SCALE);
        atomicAdd(&g_acc, (unsigned long long)qfx);
        __threadfence();
        unsigned int old = atomicAdd(&g_cnt, 1u);
        if (old == (unsigned int)(gridDim.x - 1)) {
            unsigned long long total = atomicAdd(&g_acc, 0ULL);
            out[0] = (float)((double)(long long)total * INV_NORM);
            g_cnt = 0u;      // reset for next graph replay
            g_acc = 0ULL;
        }
    }
}

extern "C" void kernel_launch(void* const* d_in, const int* in_sizes, int n_in,
                              void* d_out, int out_size) {
    const float* tf = (const float*)d_in[0];   // true_frames  (1024, 8192)
    const float* pf = (const float*)d_in[1];   // predicted_frames
    float* out = (float*)d_out;

    mse_fused_kernel<<<NBLK, NTHR>>>(tf, pf, out);
}